// round 13
// baseline (speedup 1.0000x reference)
#include <cuda_runtime.h>
#include <cuda_bf16.h>

namespace {
constexpr int C_      = 150;
constexpr int H_      = 384;
constexpr int W_      = 512;
constexpr int HW_     = H_ * W_;
constexpr int B_      = 4;
constexpr int NPIX    = B_ * HW_;        // 786432
constexpr int NGRP    = NPIX / 4;        // 196608 groups of 4 pixels
constexpr int THREADS = 256;
constexpr int BLOCKS  = 256;             // 768 chunks / 256 CTAs = exactly 3
constexpr int NCHUNK  = NGRP / THREADS;  // 768
constexpr int CPC     = NCHUNK / BLOCKS; // 3 chunks per CTA (static)
constexpr int C2      = C_ / 2;          // 75 bf16x2 per row
constexpr int NPAIRS  = C_ * C2;         // 11250 pairs in the table
constexpr int UF      = 3;               // channel-pairs per batch (75 = 25*3)
constexpr int NSTEP   = C2 / UF;         // 25
constexpr int PFD     = 2;               // prefetch distance (triple buffer)
constexpr int WPITCH  = 77;              // u32 row stride; gcd(77,32)=1
constexpr int SMEM_W  = C_ * WPITCH;     // 11550 u32
constexpr int SMEM_BYTES = SMEM_W * 4 + C_ * 4;   // ~46.8 KB
}

__device__ double       g_sum;      // zero-initialized
__device__ unsigned int g_vcnt;
__device__ unsigned int g_ticket;   // completion ticket

__global__ __launch_bounds__(THREADS, 2) void wcel_fused(
    const float* __restrict__ pred,
    const int*   __restrict__ gt_bins,
    const float* __restrict__ mask,
    const float* __restrict__ weight,
    float*       __restrict__ out)
{
    extern __shared__ unsigned int smu[];
    unsigned int* swp = smu;                                     // [C_][WPITCH]
    float*        srs = reinterpret_cast<float*>(smu + SMEM_W);  // [C_] rowsums

    const int tid = threadIdx.x;
    const size_t cstride2 = HW_ >> 1;   // 2-channel stride in float4s

    // ---- EARLY PREFETCH: start the DRAM stream before any smem staging ----
    float4 XA[PFD + 1][UF], XB[PFD + 1][UF];
    {
        const int q  = blockIdx.x * THREADS + tid;   // chunk 0 for this CTA
        const int p0 = q << 2;
        const int b  = p0 / HW_;
        const int hw = p0 - b * HW_;
        const float4* xp0 =
            reinterpret_cast<const float4*>(pred) + (((size_t)b * C_ * HW_ + hw) >> 2);
        #pragma unroll
        for (int pb = 0; pb < PFD; ++pb)
            #pragma unroll
            for (int k = 0; k < UF; ++k) {
                const size_t off = (size_t)(pb * UF + k) * cstride2;
                XA[pb][k] = __ldcs(xp0 + off);
                XB[pb][k] = __ldcs(xp0 + off + (HW_ >> 2));
            }
    }

    // Stage weight table as packed bf16 pairs (float4 reads: 2 pairs per load;
    // pairs never straddle rows since 150 floats/row is even)
    for (int i = tid; i < NPAIRS / 2; i += THREADS) {
        const float4 w4 = *reinterpret_cast<const float4*>(weight + 4 * i);
        const int pA = 2 * i,     rA = pA / C2, cA = pA - rA * C2;
        const int pB = 2 * i + 1, rB = pB / C2, cB = pB - rB * C2;
        const unsigned int a0 = __bfloat16_as_ushort(__float2bfloat16_rn(w4.x));
        const unsigned int a1 = __bfloat16_as_ushort(__float2bfloat16_rn(w4.y));
        const unsigned int b0 = __bfloat16_as_ushort(__float2bfloat16_rn(w4.z));
        const unsigned int b1 = __bfloat16_as_ushort(__float2bfloat16_rn(w4.w));
        swp[rA * WPITCH + cA] = a0 | (a1 << 16);
        swp[rB * WPITCH + cB] = b0 | (b1 << 16);
    }
    // fp32 row sums straight from gmem (L2-resident; independent of staging
    // above -> ptxas interleaves both loops, and only ONE barrier is needed)
    for (int r = tid; r < C_; r += THREADS) {
        float s = 0.f;
        const float* row = weight + r * C_;
        #pragma unroll 6
        for (int c = 0; c < C_; ++c) s += __ldg(row + c);
        srs[r] = s;
    }
    __syncthreads();

    float loc = 0.f;
    float vcf = 0.f;                    // mask is 0/1 -> count = sum(mask)

    // ---- Static schedule: CTA c handles chunks {c, c+256, c+512} ----
    #pragma unroll
    for (int ci = 0; ci < CPC; ++ci) {
        const int q  = (ci * BLOCKS + blockIdx.x) * THREADS + tid;
        const int p0 = q << 2;
        const int b  = p0 / HW_;
        const int hw = p0 - b * HW_;

        const float4* __restrict__ xp =
            reinterpret_cast<const float4*>(pred) + (((size_t)b * C_ * HW_ + hw) >> 2);

        // Early, independent loads for this chunk: mask + bins issue before
        // the 25-step pipeline so their DRAM latency is fully hidden.
        const float4 m = __ldcs(reinterpret_cast<const float4*>(mask + p0));
        const int4   g = *reinterpret_cast<const int4*>(gt_bins + p0);

        const unsigned int* __restrict__ w0 = swp + g.x * WPITCH;
        const unsigned int* __restrict__ w1 = swp + g.y * WPITCH;
        const unsigned int* __restrict__ w2 = swp + g.z * WPITCH;
        const unsigned int* __restrict__ w3 = swp + g.w * WPITCH;

        float s0 = 0.f, s1 = 0.f, s2 = 0.f, s3 = 0.f;   // sum exp(x)
        float d0 = 0.f, d1 = 0.f, d2 = 0.f, d3 = 0.f;   // dot(w_row, x)

        if (ci != 0) {                                   // chunk 0 preloaded above
            #pragma unroll
            for (int pb = 0; pb < PFD; ++pb)
                #pragma unroll
                for (int k = 0; k < UF; ++k) {
                    const size_t off = (size_t)(pb * UF + k) * cstride2;
                    XA[pb][k] = __ldcs(xp + off);
                    XB[pb][k] = __ldcs(xp + off + (HW_ >> 2));
                }
        }

        #pragma unroll
        for (int step = 0; step < NSTEP; ++step) {
            const int cur = step % (PFD + 1);
            const int nxt = (step + PFD) % (PFD + 1);
            if (step + PFD < NSTEP) {
                const int c2b = (step + PFD) * UF;
                #pragma unroll
                for (int k = 0; k < UF; ++k) {
                    const size_t off = (size_t)(c2b + k) * cstride2;
                    XA[nxt][k] = __ldcs(xp + off);
                    XB[nxt][k] = __ldcs(xp + off + (HW_ >> 2));
                }
            }
            const int c2b = step * UF;
            #pragma unroll
            for (int k = 0; k < UF; ++k) {
                const unsigned int u0 = w0[c2b + k];
                const unsigned int u1 = w1[c2b + k];
                const unsigned int u2 = w2[c2b + k];
                const unsigned int u3 = w3[c2b + k];
                const float4 xa = XA[cur][k];
                const float4 xb = XB[cur][k];

                s0 += __expf(xa.x); s0 += __expf(xb.x);
                s1 += __expf(xa.y); s1 += __expf(xb.y);
                s2 += __expf(xa.z); s2 += __expf(xb.z);
                s3 += __expf(xa.w); s3 += __expf(xb.w);

                d0 = fmaf(__uint_as_float(u0 << 16),         xa.x, d0);
                d0 = fmaf(__uint_as_float(u0 & 0xFFFF0000u), xb.x, d0);
                d1 = fmaf(__uint_as_float(u1 << 16),         xa.y, d1);
                d1 = fmaf(__uint_as_float(u1 & 0xFFFF0000u), xb.y, d1);
                d2 = fmaf(__uint_as_float(u2 << 16),         xa.z, d2);
                d2 = fmaf(__uint_as_float(u2 & 0xFFFF0000u), xb.z, d2);
                d3 = fmaf(__uint_as_float(u3 << 16),         xa.w, d3);
                d3 = fmaf(__uint_as_float(u3 & 0xFFFF0000u), xb.w, d3);
            }
        }

        loc += m.x * (d0 - __logf(s0) * srs[g.x]);
        loc += m.y * (d1 - __logf(s1) * srs[g.y]);
        loc += m.z * (d2 - __logf(s2) * srs[g.z]);
        loc += m.w * (d3 - __logf(s3) * srs[g.w]);
        vcf += m.x + m.y + m.z + m.w;
    }

    // Block reduction
    #pragma unroll
    for (int o = 16; o > 0; o >>= 1) {
        loc += __shfl_down_sync(0xffffffffu, loc, o);
        vcf += __shfl_down_sync(0xffffffffu, vcf, o);
    }
    __shared__ float s_loc[THREADS / 32];
    __shared__ float s_vc[THREADS / 32];
    const int lane = tid & 31;
    const int wid  = tid >> 5;
    if (lane == 0) { s_loc[wid] = loc; s_vc[wid] = vcf; }
    __syncthreads();

    if (tid == 0) {
        float bl = 0.f, bv = 0.f;
        #pragma unroll
        for (int i = 0; i < THREADS / 32; ++i) { bl += s_loc[i]; bv += s_vc[i]; }
        atomicAdd(&g_sum, (double)bl);
        atomicAdd(&g_vcnt, (unsigned)(bv + 0.5f));
        __threadfence();
        const unsigned old = atomicInc(&g_ticket, BLOCKS - 1);   // wraps to 0
        if (old == BLOCKS - 1) {
            out[0] = (float)(-g_sum / (double)g_vcnt);
            g_sum  = 0.0;       // self-reset for next graph replay
            g_vcnt = 0u;
        }
    }
}

extern "C" void kernel_launch(void* const* d_in, const int* in_sizes, int n_in,
                              void* d_out, int out_size) {
    const float* pred   = (const float*)d_in[0];   // pred_logit [B,C,H,W] f32
    const int*   gbins  = (const int*)  d_in[1];   // gt_bins    [B,1,H,W] i32
    // d_in[2] = gt (unused by the loss math)
    const float* mask   = (const float*)d_in[3];   // mask       [B,1,H,W] f32
    const float* weight = (const float*)d_in[4];   // weight     [C,C]     f32

    static bool attr_set = false;
    if (!attr_set) {
        cudaFuncSetAttribute(wcel_fused,
                             cudaFuncAttributeMaxDynamicSharedMemorySize,
                             SMEM_BYTES);
        attr_set = true;
    }
    wcel_fused<<<BLOCKS, THREADS, SMEM_BYTES>>>(pred, gbins, mask, weight,
                                                (float*)d_out);
}

// round 14
// speedup vs baseline: 1.1047x; 1.1047x over previous
#include <cuda_runtime.h>
#include <cuda_bf16.h>

namespace {
constexpr int C_      = 150;
constexpr int H_      = 384;
constexpr int W_      = 512;
constexpr int HW_     = H_ * W_;
constexpr int B_      = 4;
constexpr int NPIX    = B_ * HW_;        // 786432
constexpr int NGRP    = NPIX / 4;        // 196608 groups of 4 pixels
constexpr int THREADS = 256;
constexpr int BLOCKS  = 256;             // 768 chunks / 256 CTAs = exactly 3
constexpr int NCHUNK  = NGRP / THREADS;  // 768
constexpr int CPC     = NCHUNK / BLOCKS; // 3 chunks per CTA (static)
constexpr int C2      = C_ / 2;          // 75 bf16x2 per row
constexpr int NPAIRS  = C_ * C2;         // 11250 pairs in the table
constexpr int UF      = 3;               // channel-pairs per batch (75 = 25*3)
constexpr int NSTEP   = C2 / UF;         // 25
constexpr int PFD     = 2;               // prefetch distance (triple buffer)
constexpr int WPITCH  = 77;              // u32 row stride; gcd(77,32)=1
constexpr int SMEM_W  = C_ * WPITCH;     // 11550 u32
constexpr int SMEM_BYTES = SMEM_W * 4 + C_ * 4;   // ~46.8 KB
}

__device__ double       g_sum;      // zero-initialized
__device__ unsigned int g_vcnt;
__device__ unsigned int g_ticket;   // completion ticket

__global__ __launch_bounds__(THREADS, 2) void wcel_fused(
    const float* __restrict__ pred,
    const int*   __restrict__ gt_bins,
    const float* __restrict__ mask,
    const float* __restrict__ weight,
    float*       __restrict__ out)
{
    extern __shared__ unsigned int smu[];
    unsigned int* swp = smu;                                     // [C_][WPITCH]
    float*        srs = reinterpret_cast<float*>(smu + SMEM_W);  // [C_] rowsums

    const int tid = threadIdx.x;
    const size_t cstride2 = HW_ >> 1;   // 2-channel stride in float4s

    // ---- EARLY PREFETCH: start the DRAM stream before any smem staging ----
    float4 XA[PFD + 1][UF], XB[PFD + 1][UF];
    {
        const int q  = blockIdx.x * THREADS + tid;   // chunk 0 for this CTA
        const int p0 = q << 2;
        const int b  = p0 / HW_;
        const int hw = p0 - b * HW_;
        const float4* xp0 =
            reinterpret_cast<const float4*>(pred) + (((size_t)b * C_ * HW_ + hw) >> 2);
        #pragma unroll
        for (int pb = 0; pb < PFD; ++pb)
            #pragma unroll
            for (int k = 0; k < UF; ++k) {
                const size_t off = (size_t)(pb * UF + k) * cstride2;
                XA[pb][k] = __ldcs(xp0 + off);
                XB[pb][k] = __ldcs(xp0 + off + (HW_ >> 2));
            }
    }

    // Stage weight table as packed bf16 pairs (float4 reads: 2 pairs per load;
    // pairs never straddle rows since 150 floats/row is even)
    for (int i = tid; i < NPAIRS / 2; i += THREADS) {
        const float4 w4 = *reinterpret_cast<const float4*>(weight + 4 * i);
        const int pA = 2 * i,     rA = pA / C2, cA = pA - rA * C2;
        const int pB = 2 * i + 1, rB = pB / C2, cB = pB - rB * C2;
        const unsigned int a0 = __bfloat16_as_ushort(__float2bfloat16_rn(w4.x));
        const unsigned int a1 = __bfloat16_as_ushort(__float2bfloat16_rn(w4.y));
        const unsigned int b0 = __bfloat16_as_ushort(__float2bfloat16_rn(w4.z));
        const unsigned int b1 = __bfloat16_as_ushort(__float2bfloat16_rn(w4.w));
        swp[rA * WPITCH + cA] = a0 | (a1 << 16);
        swp[rB * WPITCH + cB] = b0 | (b1 << 16);
    }
    __syncthreads();
    // fp32 row sums from the staged smem table (coalesced LDS, not gmem:
    // the strided-gmem variant floods L1tex with 32-line wavefronts)
    for (int r = tid; r < C_; r += THREADS) {
        float s = 0.f;
        const unsigned int* row = swp + r * WPITCH;
        #pragma unroll 5
        for (int c2 = 0; c2 < C2; ++c2) {
            const unsigned int u = row[c2];
            s += __uint_as_float(u << 16) + __uint_as_float(u & 0xFFFF0000u);
        }
        srs[r] = s;
    }
    __syncthreads();

    float loc = 0.f;
    float vcf = 0.f;                    // mask is 0/1 -> count = sum(mask)

    // ---- Static schedule: CTA c handles chunks {c, c+256, c+512} ----
    #pragma unroll
    for (int ci = 0; ci < CPC; ++ci) {
        const int q  = (ci * BLOCKS + blockIdx.x) * THREADS + tid;
        const int p0 = q << 2;
        const int b  = p0 / HW_;
        const int hw = p0 - b * HW_;

        const float4* __restrict__ xp =
            reinterpret_cast<const float4*>(pred) + (((size_t)b * C_ * HW_ + hw) >> 2);

        // Early, independent loads for this chunk: mask + bins issue before
        // the 25-step pipeline so their DRAM latency is fully hidden.
        const float4 m = __ldcs(reinterpret_cast<const float4*>(mask + p0));
        const int4   g = *reinterpret_cast<const int4*>(gt_bins + p0);

        const unsigned int* __restrict__ w0 = swp + g.x * WPITCH;
        const unsigned int* __restrict__ w1 = swp + g.y * WPITCH;
        const unsigned int* __restrict__ w2 = swp + g.z * WPITCH;
        const unsigned int* __restrict__ w3 = swp + g.w * WPITCH;

        float s0 = 0.f, s1 = 0.f, s2 = 0.f, s3 = 0.f;   // sum exp(x)
        float d0 = 0.f, d1 = 0.f, d2 = 0.f, d3 = 0.f;   // dot(w_row, x)

        if (ci != 0) {                                   // chunk 0 preloaded above
            #pragma unroll
            for (int pb = 0; pb < PFD; ++pb)
                #pragma unroll
                for (int k = 0; k < UF; ++k) {
                    const size_t off = (size_t)(pb * UF + k) * cstride2;
                    XA[pb][k] = __ldcs(xp + off);
                    XB[pb][k] = __ldcs(xp + off + (HW_ >> 2));
                }
        }

        #pragma unroll
        for (int step = 0; step < NSTEP; ++step) {
            const int cur = step % (PFD + 1);
            const int nxt = (step + PFD) % (PFD + 1);
            if (step + PFD < NSTEP) {
                const int c2b = (step + PFD) * UF;
                #pragma unroll
                for (int k = 0; k < UF; ++k) {
                    const size_t off = (size_t)(c2b + k) * cstride2;
                    XA[nxt][k] = __ldcs(xp + off);
                    XB[nxt][k] = __ldcs(xp + off + (HW_ >> 2));
                }
            }
            const int c2b = step * UF;
            #pragma unroll
            for (int k = 0; k < UF; ++k) {
                const unsigned int u0 = w0[c2b + k];
                const unsigned int u1 = w1[c2b + k];
                const unsigned int u2 = w2[c2b + k];
                const unsigned int u3 = w3[c2b + k];
                const float4 xa = XA[cur][k];
                const float4 xb = XB[cur][k];

                s0 += __expf(xa.x); s0 += __expf(xb.x);
                s1 += __expf(xa.y); s1 += __expf(xb.y);
                s2 += __expf(xa.z); s2 += __expf(xb.z);
                s3 += __expf(xa.w); s3 += __expf(xb.w);

                d0 = fmaf(__uint_as_float(u0 << 16),         xa.x, d0);
                d0 = fmaf(__uint_as_float(u0 & 0xFFFF0000u), xb.x, d0);
                d1 = fmaf(__uint_as_float(u1 << 16),         xa.y, d1);
                d1 = fmaf(__uint_as_float(u1 & 0xFFFF0000u), xb.y, d1);
                d2 = fmaf(__uint_as_float(u2 << 16),         xa.z, d2);
                d2 = fmaf(__uint_as_float(u2 & 0xFFFF0000u), xb.z, d2);
                d3 = fmaf(__uint_as_float(u3 << 16),         xa.w, d3);
                d3 = fmaf(__uint_as_float(u3 & 0xFFFF0000u), xb.w, d3);
            }
        }

        loc += m.x * (d0 - __logf(s0) * srs[g.x]);
        loc += m.y * (d1 - __logf(s1) * srs[g.y]);
        loc += m.z * (d2 - __logf(s2) * srs[g.z]);
        loc += m.w * (d3 - __logf(s3) * srs[g.w]);
        vcf += m.x + m.y + m.z + m.w;
    }

    // Block reduction
    #pragma unroll
    for (int o = 16; o > 0; o >>= 1) {
        loc += __shfl_down_sync(0xffffffffu, loc, o);
        vcf += __shfl_down_sync(0xffffffffu, vcf, o);
    }
    __shared__ float s_loc[THREADS / 32];
    __shared__ float s_vc[THREADS / 32];
    const int lane = tid & 31;
    const int wid  = tid >> 5;
    if (lane == 0) { s_loc[wid] = loc; s_vc[wid] = vcf; }
    __syncthreads();

    if (tid == 0) {
        float bl = 0.f, bv = 0.f;
        #pragma unroll
        for (int i = 0; i < THREADS / 32; ++i) { bl += s_loc[i]; bv += s_vc[i]; }
        atomicAdd(&g_sum, (double)bl);
        atomicAdd(&g_vcnt, (unsigned)(bv + 0.5f));
        __threadfence();
        const unsigned old = atomicInc(&g_ticket, BLOCKS - 1);   // wraps to 0
        if (old == BLOCKS - 1) {
            out[0] = (float)(-g_sum / (double)g_vcnt);
            g_sum  = 0.0;       // self-reset for next graph replay
            g_vcnt = 0u;
        }
    }
}

extern "C" void kernel_launch(void* const* d_in, const int* in_sizes, int n_in,
                              void* d_out, int out_size) {
    const float* pred   = (const float*)d_in[0];   // pred_logit [B,C,H,W] f32
    const int*   gbins  = (const int*)  d_in[1];   // gt_bins    [B,1,H,W] i32
    // d_in[2] = gt (unused by the loss math)
    const float* mask   = (const float*)d_in[3];   // mask       [B,1,H,W] f32
    const float* weight = (const float*)d_in[4];   // weight     [C,C]     f32

    static bool attr_set = false;
    if (!attr_set) {
        cudaFuncSetAttribute(wcel_fused,
                             cudaFuncAttributeMaxDynamicSharedMemorySize,
                             SMEM_BYTES);
        attr_set = true;
    }
    wcel_fused<<<BLOCKS, THREADS, SMEM_BYTES>>>(pred, gbins, mask, weight,
                                                (float*)d_out);
}

// round 15
// speedup vs baseline: 1.1097x; 1.0045x over previous
#include <cuda_runtime.h>
#include <cuda_bf16.h>

namespace {
constexpr int C_      = 150;
constexpr int H_      = 384;
constexpr int W_      = 512;
constexpr int HW_     = H_ * W_;
constexpr int B_      = 4;
constexpr int NPIX    = B_ * HW_;        // 786432
constexpr int NGRP    = NPIX / 4;        // 196608 groups of 4 pixels
constexpr int THREADS = 256;
constexpr int BLOCKS  = 256;             // 768 chunks / 256 CTAs = exactly 3
constexpr int NCHUNK  = NGRP / THREADS;  // 768
constexpr int CPC     = NCHUNK / BLOCKS; // 3 chunks per CTA (static)
constexpr int C2      = C_ / 2;          // 75 bf16x2 per row
constexpr int NPAIRS  = C_ * C2;         // 11250 pairs in the table
constexpr int UF      = 3;               // channel-pairs per batch (75 = 25*3)
constexpr int NSTEP   = C2 / UF;         // 25
constexpr int PFD     = 2;               // prefetch distance (triple buffer)
constexpr int WPITCH  = 77;              // u32 row stride; gcd(77,32)=1
constexpr int SMEM_W  = C_ * WPITCH;     // 11550 u32
constexpr int SMEM_BYTES = SMEM_W * 4 + C_ * 4;   // ~46.8 KB
}

__device__ double       g_sum;      // zero-initialized
__device__ unsigned int g_vcnt;
__device__ unsigned int g_ticket;   // completion ticket

__global__ __launch_bounds__(THREADS, 2) void wcel_fused(
    const float* __restrict__ pred,
    const int*   __restrict__ gt_bins,
    const float* __restrict__ mask,
    const float* __restrict__ weight,
    float*       __restrict__ out)
{
    extern __shared__ unsigned int smu[];
    unsigned int* swp = smu;                                     // [C_][WPITCH]
    float*        srs = reinterpret_cast<float*>(smu + SMEM_W);  // [C_] rowsums

    const int tid = threadIdx.x;
    const size_t cstride2 = HW_ >> 1;   // 2-channel stride in float4s

    // ---- EARLY PREFETCH: start the DRAM stream before any smem staging ----
    float4 XA[PFD + 1][UF], XB[PFD + 1][UF];
    {
        const int q  = blockIdx.x * THREADS + tid;   // chunk 0 for this CTA
        const int p0 = q << 2;
        const int b  = p0 / HW_;
        const int hw = p0 - b * HW_;
        const float4* xp0 =
            reinterpret_cast<const float4*>(pred) + (((size_t)b * C_ * HW_ + hw) >> 2);
        #pragma unroll
        for (int pb = 0; pb < PFD; ++pb)
            #pragma unroll
            for (int k = 0; k < UF; ++k) {
                const size_t off = (size_t)(pb * UF + k) * cstride2;
                XA[pb][k] = __ldcs(xp0 + off);
                XB[pb][k] = __ldcs(xp0 + off + (HW_ >> 2));
            }
    }

    // Stage weight table as packed bf16 pairs (float4 reads: 2 pairs per load;
    // pairs never straddle rows since 150 floats/row is even)
    for (int i = tid; i < NPAIRS / 2; i += THREADS) {
        const float4 w4 = *reinterpret_cast<const float4*>(weight + 4 * i);
        const int pA = 2 * i,     rA = pA / C2, cA = pA - rA * C2;
        const int pB = 2 * i + 1, rB = pB / C2, cB = pB - rB * C2;
        const unsigned int a0 = __bfloat16_as_ushort(__float2bfloat16_rn(w4.x));
        const unsigned int a1 = __bfloat16_as_ushort(__float2bfloat16_rn(w4.y));
        const unsigned int b0 = __bfloat16_as_ushort(__float2bfloat16_rn(w4.z));
        const unsigned int b1 = __bfloat16_as_ushort(__float2bfloat16_rn(w4.w));
        swp[rA * WPITCH + cA] = a0 | (a1 << 16);
        swp[rB * WPITCH + cB] = b0 | (b1 << 16);
    }
    __syncthreads();
    // fp32 row sums from the staged smem table (coalesced LDS, not gmem:
    // the strided-gmem variant floods L1tex with 32-line wavefronts)
    for (int r = tid; r < C_; r += THREADS) {
        float s = 0.f;
        const unsigned int* row = swp + r * WPITCH;
        #pragma unroll 5
        for (int c2 = 0; c2 < C2; ++c2) {
            const unsigned int u = row[c2];
            s += __uint_as_float(u << 16) + __uint_as_float(u & 0xFFFF0000u);
        }
        srs[r] = s;
    }
    __syncthreads();

    float loc = 0.f;
    float vcf = 0.f;                    // mask is 0/1 -> count = sum(mask)

    // ---- Static schedule: CTA c handles chunks {c, c+256, c+512} ----
    #pragma unroll
    for (int ci = 0; ci < CPC; ++ci) {
        const int q  = (ci * BLOCKS + blockIdx.x) * THREADS + tid;
        const int p0 = q << 2;
        const int b  = p0 / HW_;
        const int hw = p0 - b * HW_;

        const float4* __restrict__ xp =
            reinterpret_cast<const float4*>(pred) + (((size_t)b * C_ * HW_ + hw) >> 2);

        // Early, independent loads for this chunk: mask + bins issue before
        // the 25-step pipeline so their DRAM latency is fully hidden.
        const float4 m = __ldcs(reinterpret_cast<const float4*>(mask + p0));
        const int4   g = *reinterpret_cast<const int4*>(gt_bins + p0);

        const unsigned int* __restrict__ w0 = swp + g.x * WPITCH;
        const unsigned int* __restrict__ w1 = swp + g.y * WPITCH;
        const unsigned int* __restrict__ w2 = swp + g.z * WPITCH;
        const unsigned int* __restrict__ w3 = swp + g.w * WPITCH;

        float s0 = 0.f, s1 = 0.f, s2 = 0.f, s3 = 0.f;   // sum exp(x)
        float d0 = 0.f, d1 = 0.f, d2 = 0.f, d3 = 0.f;   // dot(w_row, x)

        if (ci != 0) {                                   // chunk 0 preloaded above
            #pragma unroll
            for (int pb = 0; pb < PFD; ++pb)
                #pragma unroll
                for (int k = 0; k < UF; ++k) {
                    const size_t off = (size_t)(pb * UF + k) * cstride2;
                    XA[pb][k] = __ldcs(xp + off);
                    XB[pb][k] = __ldcs(xp + off + (HW_ >> 2));
                }
        }

        #pragma unroll
        for (int step = 0; step < NSTEP; ++step) {
            const int cur = step % (PFD + 1);
            const int nxt = (step + PFD) % (PFD + 1);
            if (step + PFD < NSTEP) {
                const int c2b = (step + PFD) * UF;
                #pragma unroll
                for (int k = 0; k < UF; ++k) {
                    const size_t off = (size_t)(c2b + k) * cstride2;
                    XA[nxt][k] = __ldcs(xp + off);
                    XB[nxt][k] = __ldcs(xp + off + (HW_ >> 2));
                }
            }
            const int c2b = step * UF;
            #pragma unroll
            for (int k = 0; k < UF; ++k) {
                const unsigned int u0 = w0[c2b + k];
                const unsigned int u1 = w1[c2b + k];
                const unsigned int u2 = w2[c2b + k];
                const unsigned int u3 = w3[c2b + k];
                const float4 xa = XA[cur][k];
                const float4 xb = XB[cur][k];

                s0 += __expf(xa.x); s0 += __expf(xb.x);
                s1 += __expf(xa.y); s1 += __expf(xb.y);
                s2 += __expf(xa.z); s2 += __expf(xb.z);
                s3 += __expf(xa.w); s3 += __expf(xb.w);

                d0 = fmaf(__uint_as_float(u0 << 16),         xa.x, d0);
                d0 = fmaf(__uint_as_float(u0 & 0xFFFF0000u), xb.x, d0);
                d1 = fmaf(__uint_as_float(u1 << 16),         xa.y, d1);
                d1 = fmaf(__uint_as_float(u1 & 0xFFFF0000u), xb.y, d1);
                d2 = fmaf(__uint_as_float(u2 << 16),         xa.z, d2);
                d2 = fmaf(__uint_as_float(u2 & 0xFFFF0000u), xb.z, d2);
                d3 = fmaf(__uint_as_float(u3 << 16),         xa.w, d3);
                d3 = fmaf(__uint_as_float(u3 & 0xFFFF0000u), xb.w, d3);
            }
        }

        loc += m.x * (d0 - __logf(s0) * srs[g.x]);
        loc += m.y * (d1 - __logf(s1) * srs[g.y]);
        loc += m.z * (d2 - __logf(s2) * srs[g.z]);
        loc += m.w * (d3 - __logf(s3) * srs[g.w]);
        vcf += m.x + m.y + m.z + m.w;
    }

    // Block reduction
    #pragma unroll
    for (int o = 16; o > 0; o >>= 1) {
        loc += __shfl_down_sync(0xffffffffu, loc, o);
        vcf += __shfl_down_sync(0xffffffffu, vcf, o);
    }
    __shared__ float s_loc[THREADS / 32];
    __shared__ float s_vc[THREADS / 32];
    const int lane = tid & 31;
    const int wid  = tid >> 5;
    if (lane == 0) { s_loc[wid] = loc; s_vc[wid] = vcf; }
    __syncthreads();

    if (tid == 0) {
        float bl = 0.f, bv = 0.f;
        #pragma unroll
        for (int i = 0; i < THREADS / 32; ++i) { bl += s_loc[i]; bv += s_vc[i]; }
        atomicAdd(&g_sum, (double)bl);
        atomicAdd(&g_vcnt, (unsigned)(bv + 0.5f));
        __threadfence();
        const unsigned old = atomicInc(&g_ticket, BLOCKS - 1);   // wraps to 0
        if (old == BLOCKS - 1) {
            out[0] = (float)(-g_sum / (double)g_vcnt);
            g_sum  = 0.0;       // self-reset for next graph replay
            g_vcnt = 0u;
        }
    }
}

extern "C" void kernel_launch(void* const* d_in, const int* in_sizes, int n_in,
                              void* d_out, int out_size) {
    const float* pred   = (const float*)d_in[0];   // pred_logit [B,C,H,W] f32
    const int*   gbins  = (const int*)  d_in[1];   // gt_bins    [B,1,H,W] i32
    // d_in[2] = gt (unused by the loss math)
    const float* mask   = (const float*)d_in[3];   // mask       [B,1,H,W] f32
    const float* weight = (const float*)d_in[4];   // weight     [C,C]     f32

    static bool attr_set = false;
    if (!attr_set) {
        cudaFuncSetAttribute(wcel_fused,
                             cudaFuncAttributeMaxDynamicSharedMemorySize,
                             SMEM_BYTES);
        attr_set = true;
    }
    wcel_fused<<<BLOCKS, THREADS, SMEM_BYTES>>>(pred, gbins, mask, weight,
                                                (float*)d_out);
}

// round 16
// speedup vs baseline: 1.1133x; 1.0033x over previous
#include <cuda_runtime.h>
#include <cuda_bf16.h>

namespace {
constexpr int C_      = 150;
constexpr int H_      = 384;
constexpr int W_      = 512;
constexpr int HW_     = H_ * W_;
constexpr int B_      = 4;
constexpr int NPIX    = B_ * HW_;        // 786432
constexpr int NGRP    = NPIX / 4;        // 196608 groups of 4 pixels
constexpr int THREADS = 256;
constexpr int BLOCKS  = 256;             // 768 chunks / 256 CTAs = exactly 3
constexpr int NCHUNK  = NGRP / THREADS;  // 768
constexpr int CPC     = NCHUNK / BLOCKS; // 3 chunks per CTA (static)
constexpr int C2      = C_ / 2;          // 75 bf16x2 per row
constexpr int NPAIRS  = C_ * C2;         // 11250 pairs in the table
constexpr int UF      = 3;               // channel-pairs per batch (75 = 25*3)
constexpr int NSTEP   = C2 / UF;         // 25
constexpr int PFD     = 2;               // prefetch distance (triple buffer)
constexpr int WPITCH  = 77;              // u32 row stride; gcd(77,32)=1
constexpr int SMEM_W  = C_ * WPITCH;     // 11550 u32
constexpr int SMEM_BYTES = SMEM_W * 4 + C_ * 4;   // ~46.8 KB
}

__device__ double       g_sum;      // zero-initialized
__device__ unsigned int g_vcnt;
__device__ unsigned int g_ticket;   // completion ticket

__global__ __launch_bounds__(THREADS, 2) void wcel_fused(
    const float* __restrict__ pred,
    const int*   __restrict__ gt_bins,
    const float* __restrict__ mask,
    const float* __restrict__ weight,
    float*       __restrict__ out)
{
    extern __shared__ unsigned int smu[];
    unsigned int* swp = smu;                                     // [C_][WPITCH]
    float*        srs = reinterpret_cast<float*>(smu + SMEM_W);  // [C_] rowsums

    const int tid = threadIdx.x;
    const size_t cstride2 = HW_ >> 1;   // 2-channel stride in float4s

    // ---- EARLY PREFETCH: start the DRAM stream before any smem staging ----
    float4 XA[PFD + 1][UF], XB[PFD + 1][UF];
    {
        const int q  = blockIdx.x * THREADS + tid;   // chunk 0 for this CTA
        const int p0 = q << 2;
        const int b  = p0 / HW_;
        const int hw = p0 - b * HW_;
        const float4* xp0 =
            reinterpret_cast<const float4*>(pred) + (((size_t)b * C_ * HW_ + hw) >> 2);
        #pragma unroll
        for (int pb = 0; pb < PFD; ++pb)
            #pragma unroll
            for (int k = 0; k < UF; ++k) {
                const size_t off = (size_t)(pb * UF + k) * cstride2;
                XA[pb][k] = __ldcs(xp0 + off);
                XB[pb][k] = __ldcs(xp0 + off + (HW_ >> 2));
            }
    }

    // Stage weight table as packed bf16 pairs (float4 reads: 2 pairs per load;
    // pairs never straddle rows since 150 floats/row is even)
    for (int i = tid; i < NPAIRS / 2; i += THREADS) {
        const float4 w4 = *reinterpret_cast<const float4*>(weight + 4 * i);
        const int pA = 2 * i,     rA = pA / C2, cA = pA - rA * C2;
        const int pB = 2 * i + 1, rB = pB / C2, cB = pB - rB * C2;
        const unsigned int a0 = __bfloat16_as_ushort(__float2bfloat16_rn(w4.x));
        const unsigned int a1 = __bfloat16_as_ushort(__float2bfloat16_rn(w4.y));
        const unsigned int b0 = __bfloat16_as_ushort(__float2bfloat16_rn(w4.z));
        const unsigned int b1 = __bfloat16_as_ushort(__float2bfloat16_rn(w4.w));
        swp[rA * WPITCH + cA] = a0 | (a1 << 16);
        swp[rB * WPITCH + cB] = b0 | (b1 << 16);
    }
    __syncthreads();
    // fp32 row sums from the staged smem table (coalesced LDS, not gmem:
    // the strided-gmem variant floods L1tex with 32-line wavefronts)
    for (int r = tid; r < C_; r += THREADS) {
        float s = 0.f;
        const unsigned int* row = swp + r * WPITCH;
        #pragma unroll 5
        for (int c2 = 0; c2 < C2; ++c2) {
            const unsigned int u = row[c2];
            s += __uint_as_float(u << 16) + __uint_as_float(u & 0xFFFF0000u);
        }
        srs[r] = s;
    }
    __syncthreads();

    float loc = 0.f;
    float vcf = 0.f;                    // mask is 0/1 -> count = sum(mask)

    // ---- Static schedule: CTA c handles chunks {c, c+256, c+512} ----
    #pragma unroll
    for (int ci = 0; ci < CPC; ++ci) {
        const int q  = (ci * BLOCKS + blockIdx.x) * THREADS + tid;
        const int p0 = q << 2;
        const int b  = p0 / HW_;
        const int hw = p0 - b * HW_;

        const float4* __restrict__ xp =
            reinterpret_cast<const float4*>(pred) + (((size_t)b * C_ * HW_ + hw) >> 2);

        // Early, independent loads for this chunk: mask + bins issue before
        // the 25-step pipeline so their DRAM latency is fully hidden.
        const float4 m = __ldcs(reinterpret_cast<const float4*>(mask + p0));
        const int4   g = *reinterpret_cast<const int4*>(gt_bins + p0);

        const unsigned int* __restrict__ w0 = swp + g.x * WPITCH;
        const unsigned int* __restrict__ w1 = swp + g.y * WPITCH;
        const unsigned int* __restrict__ w2 = swp + g.z * WPITCH;
        const unsigned int* __restrict__ w3 = swp + g.w * WPITCH;

        float s0 = 0.f, s1 = 0.f, s2 = 0.f, s3 = 0.f;   // sum exp(x)
        float d0 = 0.f, d1 = 0.f, d2 = 0.f, d3 = 0.f;   // dot(w_row, x)

        if (ci != 0) {                                   // chunk 0 preloaded above
            #pragma unroll
            for (int pb = 0; pb < PFD; ++pb)
                #pragma unroll
                for (int k = 0; k < UF; ++k) {
                    const size_t off = (size_t)(pb * UF + k) * cstride2;
                    XA[pb][k] = __ldcs(xp + off);
                    XB[pb][k] = __ldcs(xp + off + (HW_ >> 2));
                }
        }

        #pragma unroll
        for (int step = 0; step < NSTEP; ++step) {
            const int cur = step % (PFD + 1);
            const int nxt = (step + PFD) % (PFD + 1);
            if (step + PFD < NSTEP) {
                const int c2b = (step + PFD) * UF;
                #pragma unroll
                for (int k = 0; k < UF; ++k) {
                    const size_t off = (size_t)(c2b + k) * cstride2;
                    XA[nxt][k] = __ldcs(xp + off);
                    XB[nxt][k] = __ldcs(xp + off + (HW_ >> 2));
                }
            }
            const int c2b = step * UF;
            #pragma unroll
            for (int k = 0; k < UF; ++k) {
                const unsigned int u0 = w0[c2b + k];
                const unsigned int u1 = w1[c2b + k];
                const unsigned int u2 = w2[c2b + k];
                const unsigned int u3 = w3[c2b + k];
                const float4 xa = XA[cur][k];
                const float4 xb = XB[cur][k];

                s0 += __expf(xa.x); s0 += __expf(xb.x);
                s1 += __expf(xa.y); s1 += __expf(xb.y);
                s2 += __expf(xa.z); s2 += __expf(xb.z);
                s3 += __expf(xa.w); s3 += __expf(xb.w);

                d0 = fmaf(__uint_as_float(u0 << 16),         xa.x, d0);
                d0 = fmaf(__uint_as_float(u0 & 0xFFFF0000u), xb.x, d0);
                d1 = fmaf(__uint_as_float(u1 << 16),         xa.y, d1);
                d1 = fmaf(__uint_as_float(u1 & 0xFFFF0000u), xb.y, d1);
                d2 = fmaf(__uint_as_float(u2 << 16),         xa.z, d2);
                d2 = fmaf(__uint_as_float(u2 & 0xFFFF0000u), xb.z, d2);
                d3 = fmaf(__uint_as_float(u3 << 16),         xa.w, d3);
                d3 = fmaf(__uint_as_float(u3 & 0xFFFF0000u), xb.w, d3);
            }
        }

        loc += m.x * (d0 - __logf(s0) * srs[g.x]);
        loc += m.y * (d1 - __logf(s1) * srs[g.y]);
        loc += m.z * (d2 - __logf(s2) * srs[g.z]);
        loc += m.w * (d3 - __logf(s3) * srs[g.w]);
        vcf += m.x + m.y + m.z + m.w;
    }

    // Block reduction
    #pragma unroll
    for (int o = 16; o > 0; o >>= 1) {
        loc += __shfl_down_sync(0xffffffffu, loc, o);
        vcf += __shfl_down_sync(0xffffffffu, vcf, o);
    }
    __shared__ float s_loc[THREADS / 32];
    __shared__ float s_vc[THREADS / 32];
    const int lane = tid & 31;
    const int wid  = tid >> 5;
    if (lane == 0) { s_loc[wid] = loc; s_vc[wid] = vcf; }
    __syncthreads();

    if (tid == 0) {
        float bl = 0.f, bv = 0.f;
        #pragma unroll
        for (int i = 0; i < THREADS / 32; ++i) { bl += s_loc[i]; bv += s_vc[i]; }
        atomicAdd(&g_sum, (double)bl);
        atomicAdd(&g_vcnt, (unsigned)(bv + 0.5f));
        __threadfence();
        const unsigned old = atomicInc(&g_ticket, BLOCKS - 1);   // wraps to 0
        if (old == BLOCKS - 1) {
            out[0] = (float)(-g_sum / (double)g_vcnt);
            g_sum  = 0.0;       // self-reset for next graph replay
            g_vcnt = 0u;
        }
    }
}

extern "C" void kernel_launch(void* const* d_in, const int* in_sizes, int n_in,
                              void* d_out, int out_size) {
    const float* pred   = (const float*)d_in[0];   // pred_logit [B,C,H,W] f32
    const int*   gbins  = (const int*)  d_in[1];   // gt_bins    [B,1,H,W] i32
    // d_in[2] = gt (unused by the loss math)
    const float* mask   = (const float*)d_in[3];   // mask       [B,1,H,W] f32
    const float* weight = (const float*)d_in[4];   // weight     [C,C]     f32

    static bool attr_set = false;
    if (!attr_set) {
        cudaFuncSetAttribute(wcel_fused,
                             cudaFuncAttributeMaxDynamicSharedMemorySize,
                             SMEM_BYTES);
        attr_set = true;
    }
    wcel_fused<<<BLOCKS, THREADS, SMEM_BYTES>>>(pred, gbins, mask, weight,
                                                (float*)d_out);
}

// round 17
// speedup vs baseline: 1.1366x; 1.0210x over previous
#include <cuda_runtime.h>
#include <cuda_bf16.h>

namespace {
constexpr int C_      = 150;
constexpr int H_      = 384;
constexpr int W_      = 512;
constexpr int HW_     = H_ * W_;
constexpr int B_      = 4;
constexpr int NPIX    = B_ * HW_;        // 786432
constexpr int NGRP    = NPIX / 4;        // 196608 groups of 4 pixels
constexpr int THREADS = 256;
constexpr int BLOCKS  = 256;             // 768 chunks / 256 CTAs = exactly 3
constexpr int NCHUNK  = NGRP / THREADS;  // 768
constexpr int CPC     = NCHUNK / BLOCKS; // 3 chunks per CTA (static)
constexpr int C2      = C_ / 2;          // 75 bf16x2 per row
constexpr int NPAIRS  = C_ * C2;         // 11250 pairs in the table
constexpr int UF      = 3;               // channel-pairs per batch (75 = 25*3)
constexpr int NSTEP   = C2 / UF;         // 25
constexpr int PFD     = 2;               // prefetch distance (triple buffer)
constexpr int WPITCH  = 77;              // u32 row stride; gcd(77,32)=1
constexpr int SMEM_W  = C_ * WPITCH;     // 11550 u32
constexpr int SMEM_BYTES = SMEM_W * 4 + C_ * 4;   // ~46.8 KB
}

__device__ double       g_sum;      // zero-initialized
__device__ unsigned int g_vcnt;
__device__ unsigned int g_ticket;   // completion ticket

__global__ __launch_bounds__(THREADS, 2) void wcel_fused(
    const float* __restrict__ pred,
    const int*   __restrict__ gt_bins,
    const float* __restrict__ mask,
    const float* __restrict__ weight,
    float*       __restrict__ out)
{
    extern __shared__ unsigned int smu[];
    unsigned int* swp = smu;                                     // [C_][WPITCH]
    float*        srs = reinterpret_cast<float*>(smu + SMEM_W);  // [C_] rowsums

    const int tid = threadIdx.x;
    const size_t cstride2 = HW_ >> 1;   // 2-channel stride in float4s

    // ---- EARLY PREFETCH: start the DRAM stream before any smem staging ----
    float4 XA[PFD + 1][UF], XB[PFD + 1][UF];
    {
        const int q  = blockIdx.x * THREADS + tid;   // chunk 0 for this CTA
        const int p0 = q << 2;
        const int b  = p0 / HW_;
        const int hw = p0 - b * HW_;
        const float4* xp0 =
            reinterpret_cast<const float4*>(pred) + (((size_t)b * C_ * HW_ + hw) >> 2);
        #pragma unroll
        for (int pb = 0; pb < PFD; ++pb)
            #pragma unroll
            for (int k = 0; k < UF; ++k) {
                const size_t off = (size_t)(pb * UF + k) * cstride2;
                XA[pb][k] = __ldcs(xp0 + off);
                XB[pb][k] = __ldcs(xp0 + off + (HW_ >> 2));
            }
    }

    // Stage weight table as packed bf16 pairs (float4 reads: 2 pairs per load;
    // pairs never straddle rows since 150 floats/row is even)
    for (int i = tid; i < NPAIRS / 2; i += THREADS) {
        const float4 w4 = *reinterpret_cast<const float4*>(weight + 4 * i);
        const int pA = 2 * i,     rA = pA / C2, cA = pA - rA * C2;
        const int pB = 2 * i + 1, rB = pB / C2, cB = pB - rB * C2;
        const unsigned int a0 = __bfloat16_as_ushort(__float2bfloat16_rn(w4.x));
        const unsigned int a1 = __bfloat16_as_ushort(__float2bfloat16_rn(w4.y));
        const unsigned int b0 = __bfloat16_as_ushort(__float2bfloat16_rn(w4.z));
        const unsigned int b1 = __bfloat16_as_ushort(__float2bfloat16_rn(w4.w));
        swp[rA * WPITCH + cA] = a0 | (a1 << 16);
        swp[rB * WPITCH + cB] = b0 | (b1 << 16);
    }
    __syncthreads();
    // fp32 row sums from the staged smem table (coalesced LDS, not gmem:
    // the strided-gmem variant floods L1tex with 32-line wavefronts)
    for (int r = tid; r < C_; r += THREADS) {
        float s = 0.f;
        const unsigned int* row = swp + r * WPITCH;
        #pragma unroll 5
        for (int c2 = 0; c2 < C2; ++c2) {
            const unsigned int u = row[c2];
            s += __uint_as_float(u << 16) + __uint_as_float(u & 0xFFFF0000u);
        }
        srs[r] = s;
    }
    __syncthreads();

    float loc = 0.f;
    float vcf = 0.f;                    // mask is 0/1 -> count = sum(mask)

    // ---- Static schedule: CTA c handles chunks {c, c+256, c+512} ----
    #pragma unroll
    for (int ci = 0; ci < CPC; ++ci) {
        const int q  = (ci * BLOCKS + blockIdx.x) * THREADS + tid;
        const int p0 = q << 2;
        const int b  = p0 / HW_;
        const int hw = p0 - b * HW_;

        const float4* __restrict__ xp =
            reinterpret_cast<const float4*>(pred) + (((size_t)b * C_ * HW_ + hw) >> 2);

        // Early, independent loads for this chunk: mask + bins issue before
        // the 25-step pipeline so their DRAM latency is fully hidden.
        const float4 m = __ldcs(reinterpret_cast<const float4*>(mask + p0));
        const int4   g = *reinterpret_cast<const int4*>(gt_bins + p0);

        const unsigned int* __restrict__ w0 = swp + g.x * WPITCH;
        const unsigned int* __restrict__ w1 = swp + g.y * WPITCH;
        const unsigned int* __restrict__ w2 = swp + g.z * WPITCH;
        const unsigned int* __restrict__ w3 = swp + g.w * WPITCH;

        float s0 = 0.f, s1 = 0.f, s2 = 0.f, s3 = 0.f;   // sum exp(x)
        float d0 = 0.f, d1 = 0.f, d2 = 0.f, d3 = 0.f;   // dot(w_row, x)

        if (ci != 0) {                                   // chunk 0 preloaded above
            #pragma unroll
            for (int pb = 0; pb < PFD; ++pb)
                #pragma unroll
                for (int k = 0; k < UF; ++k) {
                    const size_t off = (size_t)(pb * UF + k) * cstride2;
                    XA[pb][k] = __ldcs(xp + off);
                    XB[pb][k] = __ldcs(xp + off + (HW_ >> 2));
                }
        }

        #pragma unroll
        for (int step = 0; step < NSTEP; ++step) {
            const int cur = step % (PFD + 1);
            const int nxt = (step + PFD) % (PFD + 1);
            if (step + PFD < NSTEP) {
                const int c2b = (step + PFD) * UF;
                #pragma unroll
                for (int k = 0; k < UF; ++k) {
                    const size_t off = (size_t)(c2b + k) * cstride2;
                    XA[nxt][k] = __ldcs(xp + off);
                    XB[nxt][k] = __ldcs(xp + off + (HW_ >> 2));
                }
            }
            const int c2b = step * UF;
            #pragma unroll
            for (int k = 0; k < UF; ++k) {
                const unsigned int u0 = w0[c2b + k];
                const unsigned int u1 = w1[c2b + k];
                const unsigned int u2 = w2[c2b + k];
                const unsigned int u3 = w3[c2b + k];
                const float4 xa = XA[cur][k];
                const float4 xb = XB[cur][k];

                s0 += __expf(xa.x); s0 += __expf(xb.x);
                s1 += __expf(xa.y); s1 += __expf(xb.y);
                s2 += __expf(xa.z); s2 += __expf(xb.z);
                s3 += __expf(xa.w); s3 += __expf(xb.w);

                d0 = fmaf(__uint_as_float(u0 << 16),         xa.x, d0);
                d0 = fmaf(__uint_as_float(u0 & 0xFFFF0000u), xb.x, d0);
                d1 = fmaf(__uint_as_float(u1 << 16),         xa.y, d1);
                d1 = fmaf(__uint_as_float(u1 & 0xFFFF0000u), xb.y, d1);
                d2 = fmaf(__uint_as_float(u2 << 16),         xa.z, d2);
                d2 = fmaf(__uint_as_float(u2 & 0xFFFF0000u), xb.z, d2);
                d3 = fmaf(__uint_as_float(u3 << 16),         xa.w, d3);
                d3 = fmaf(__uint_as_float(u3 & 0xFFFF0000u), xb.w, d3);
            }
        }

        loc += m.x * (d0 - __logf(s0) * srs[g.x]);
        loc += m.y * (d1 - __logf(s1) * srs[g.y]);
        loc += m.z * (d2 - __logf(s2) * srs[g.z]);
        loc += m.w * (d3 - __logf(s3) * srs[g.w]);
        vcf += m.x + m.y + m.z + m.w;
    }

    // Block reduction
    #pragma unroll
    for (int o = 16; o > 0; o >>= 1) {
        loc += __shfl_down_sync(0xffffffffu, loc, o);
        vcf += __shfl_down_sync(0xffffffffu, vcf, o);
    }
    __shared__ float s_loc[THREADS / 32];
    __shared__ float s_vc[THREADS / 32];
    const int lane = tid & 31;
    const int wid  = tid >> 5;
    if (lane == 0) { s_loc[wid] = loc; s_vc[wid] = vcf; }
    __syncthreads();

    if (tid == 0) {
        float bl = 0.f, bv = 0.f;
        #pragma unroll
        for (int i = 0; i < THREADS / 32; ++i) { bl += s_loc[i]; bv += s_vc[i]; }
        atomicAdd(&g_sum, (double)bl);
        atomicAdd(&g_vcnt, (unsigned)(bv + 0.5f));
        __threadfence();
        const unsigned old = atomicInc(&g_ticket, BLOCKS - 1);   // wraps to 0
        if (old == BLOCKS - 1) {
            out[0] = (float)(-g_sum / (double)g_vcnt);
            g_sum  = 0.0;       // self-reset for next graph replay
            g_vcnt = 0u;
        }
    }
}

extern "C" void kernel_launch(void* const* d_in, const int* in_sizes, int n_in,
                              void* d_out, int out_size) {
    const float* pred   = (const float*)d_in[0];   // pred_logit [B,C,H,W] f32
    const int*   gbins  = (const int*)  d_in[1];   // gt_bins    [B,1,H,W] i32
    // d_in[2] = gt (unused by the loss math)
    const float* mask   = (const float*)d_in[3];   // mask       [B,1,H,W] f32
    const float* weight = (const float*)d_in[4];   // weight     [C,C]     f32

    static bool attr_set = false;
    if (!attr_set) {
        cudaFuncSetAttribute(wcel_fused,
                             cudaFuncAttributeMaxDynamicSharedMemorySize,
                             SMEM_BYTES);
        attr_set = true;
    }
    wcel_fused<<<BLOCKS, THREADS, SMEM_BYTES>>>(pred, gbins, mask, weight,
                                                (float*)d_out);
}